// round 2
// baseline (speedup 1.0000x reference)
#include <cuda_runtime.h>

#define NN 100000
#define NE 1600000
#define CH 64

// Scratch: h = x + segment_sum(x[src], dst). 25.6 MB device global (no allocs allowed).
__device__ float g_agg[(size_t)NN * CH];
__device__ int   g_idx_is64;

// ---------------------------------------------------------------------------
// Kernel 0: detect whether edge_index is int64 or int32 (JAX x64-off narrows
// jnp.int64 -> int32). If the first 64 int64-interpreted words are all < NN,
// it's real int64; for int32 data the odds of that are ~0.
// ---------------------------------------------------------------------------
__global__ void detect_k(const unsigned long long* __restrict__ ei) {
    if (threadIdx.x == 0 && blockIdx.x == 0) {
        int is64 = 1;
        #pragma unroll 8
        for (int i = 0; i < 64; i++)
            if (ei[i] >= (unsigned long long)NN) { is64 = 0; break; }
        g_idx_is64 = is64;
    }
}

// ---------------------------------------------------------------------------
// Kernel 1: agg <- x   (so after scatter, g_agg holds h = x + agg directly)
// ---------------------------------------------------------------------------
__global__ void init_agg_k(const float4* __restrict__ x) {
    int i = blockIdx.x * blockDim.x + threadIdx.x;
    if (i < NN * CH / 4) reinterpret_cast<float4*>(g_agg)[i] = x[i];
}

// ---------------------------------------------------------------------------
// Kernel 2: scatter-add. One thread per (edge, 4-channel group):
// 16 consecutive threads cover one edge's 256B row (coalesced gather),
// vector reduction red.global.add.v4.f32 -> 4x fewer L2 atomic lane-ops.
// ---------------------------------------------------------------------------
__global__ void scatter_k(const float4* __restrict__ x,
                          const void* __restrict__ eiv) {
    int tid = blockIdx.x * blockDim.x + threadIdx.x;
    if (tid >= NE * 16) return;          // 25.6M threads
    int e = tid >> 4;
    int g = tid & 15;
    int src, dst;
    if (g_idx_is64) {
        const long long* ei = (const long long*)eiv;
        src = (int)__ldg(&ei[e]);
        dst = (int)__ldg(&ei[NE + e]);
    } else {
        const int* ei = (const int*)eiv;
        src = __ldg(&ei[e]);
        dst = __ldg(&ei[NE + e]);
    }
    float4 v = x[src * 16 + g];
    float* p = g_agg + (size_t)dst * CH + g * 4;
    asm volatile("red.global.add.v4.f32 [%0], {%1,%2,%3,%4};"
                 :: "l"(p), "f"(v.x), "f"(v.y), "f"(v.z), "f"(v.w)
                 : "memory");
}

// ---------------------------------------------------------------------------
// Kernel 3: fused MLP + gate.
// 256 threads = 16 nodes x 16 thread-groups; each thread owns 4 output
// channels (float4 accumulator). Weights staged once per block in SMEM.
// ---------------------------------------------------------------------------
#define NODES_PER_ITER 16
#define TPB 256

__global__ void __launch_bounds__(TPB)
mlp_k(const float* __restrict__ W1, const float* __restrict__ b1,
      const float* __restrict__ W2, const float* __restrict__ b2,
      const float* __restrict__ alpha, float* __restrict__ out,
      int out_size) {
    __shared__ float sW1[CH * CH];
    __shared__ float sW2[CH * CH];
    __shared__ float sb1[CH];
    __shared__ float sb2[CH];
    __shared__ float hs [NODES_PER_ITER][68];
    __shared__ float h1s[NODES_PER_ITER][68];

    const int tid = threadIdx.x;
    for (int i = tid; i < CH * CH; i += TPB) {
        sW1[i] = W1[i];
        sW2[i] = W2[i];
    }
    if (tid < CH) { sb1[tid] = b1[tid]; sb2[tid] = b2[tid]; }
    const float gate = 1.0f / (1.0f + expf(-alpha[0]));
    __syncthreads();

    const int r  = tid >> 4;   // node lane within block tile: 0..15
    const int t  = tid & 15;   // channel group: 0..15
    const int j4 = t * 4;      // owns channels j4..j4+3

    for (int base = blockIdx.x * NODES_PER_ITER; base < NN;
         base += gridDim.x * NODES_PER_ITER) {
        const int node = base + r;

        if (node < NN) {
            float4 v = *reinterpret_cast<const float4*>(
                g_agg + (size_t)node * CH + j4);
            *reinterpret_cast<float4*>(&hs[r][j4]) = v;
        }
        __syncthreads();

        // ---- layer 1: h1 = relu(h @ W1 + b1) ----
        float4 a1 = *reinterpret_cast<const float4*>(&sb1[j4]);
        #pragma unroll
        for (int k = 0; k < CH; k++) {
            const float hk = hs[r][k];
            const float4 w = *reinterpret_cast<const float4*>(&sW1[k * CH + j4]);
            a1.x += hk * w.x; a1.y += hk * w.y;
            a1.z += hk * w.z; a1.w += hk * w.w;
        }
        a1.x = fmaxf(a1.x, 0.0f); a1.y = fmaxf(a1.y, 0.0f);
        a1.z = fmaxf(a1.z, 0.0f); a1.w = fmaxf(a1.w, 0.0f);
        *reinterpret_cast<float4*>(&h1s[r][j4]) = a1;
        __syncthreads();

        // ---- layer 2: out = gate * (h1 @ W2 + b2) ----
        float4 a2 = *reinterpret_cast<const float4*>(&sb2[j4]);
        #pragma unroll
        for (int k = 0; k < CH; k++) {
            const float hk = h1s[r][k];
            const float4 w = *reinterpret_cast<const float4*>(&sW2[k * CH + j4]);
            a2.x += hk * w.x; a2.y += hk * w.y;
            a2.z += hk * w.z; a2.w += hk * w.w;
        }
        if (node < NN) {
            float4 o = make_float4(gate * a2.x, gate * a2.y,
                                   gate * a2.z, gate * a2.w);
            *reinterpret_cast<float4*>(out + (size_t)node * CH + j4) = o;
        }
        __syncthreads();   // protect hs/h1s before next tile overwrites
    }

    // Tail: reference also returns gate (flattened after the main output).
    const int extra = out_size - NN * CH;
    if (blockIdx.x == 0 && tid < extra) out[NN * CH + tid] = gate;
}

// ---------------------------------------------------------------------------
extern "C" void kernel_launch(void* const* d_in, const int* in_sizes, int n_in,
                              void* d_out, int out_size) {
    const float* x     = (const float*)d_in[0];
    const void*  ei    = d_in[1];
    const float* W1    = (const float*)d_in[2];
    const float* b1    = (const float*)d_in[3];
    const float* W2    = (const float*)d_in[4];
    const float* b2    = (const float*)d_in[5];
    const float* alpha = (const float*)d_in[6];
    float*       out   = (float*)d_out;

    detect_k<<<1, 32>>>((const unsigned long long*)ei);

    init_agg_k<<<(NN * CH / 4 + 255) / 256, 256>>>(
        reinterpret_cast<const float4*>(x));

    scatter_k<<<(NE * 16 + 255) / 256, 256>>>(
        reinterpret_cast<const float4*>(x), ei);

    mlp_k<<<592, TPB>>>(W1, b1, W2, b2, alpha, out, out_size);
}

// round 3
// speedup vs baseline: 1.4214x; 1.4214x over previous
#include <cuda_runtime.h>

#define NN 100000
#define NE 1600000
#define CH 64

// Scratch: h = x + segment_sum(x[src], dst). 25.6 MB device global (no allocs allowed).
__device__ float g_agg[(size_t)NN * CH];
__device__ int   g_idx_is64;

// ---------------------------------------------------------------------------
// Kernel 0: detect int64-vs-int32 edge_index (JAX x64-off narrows to int32).
// ---------------------------------------------------------------------------
__global__ void detect_k(const unsigned long long* __restrict__ ei) {
    if (threadIdx.x == 0 && blockIdx.x == 0) {
        int is64 = 1;
        for (int i = 0; i < 64; i++)
            if (ei[i] >= (unsigned long long)NN) { is64 = 0; break; }
        g_idx_is64 = is64;
    }
}

// ---------------------------------------------------------------------------
// Kernel 1: agg <- x
// ---------------------------------------------------------------------------
__global__ void init_agg_k(const float4* __restrict__ x) {
    int i = blockIdx.x * blockDim.x + threadIdx.x;
    if (i < NN * CH / 4) reinterpret_cast<float4*>(g_agg)[i] = x[i];
}

// ---------------------------------------------------------------------------
// Kernel 2: scatter-add, red.global.add.v4.f32 (L2-BW bound, ~80us).
// ---------------------------------------------------------------------------
__global__ void scatter_k(const float4* __restrict__ x,
                          const void* __restrict__ eiv) {
    int tid = blockIdx.x * blockDim.x + threadIdx.x;
    if (tid >= NE * 16) return;
    int e = tid >> 4;
    int g = tid & 15;
    int src, dst;
    if (g_idx_is64) {
        const long long* ei = (const long long*)eiv;
        src = (int)__ldg(&ei[e]);
        dst = (int)__ldg(&ei[NE + e]);
    } else {
        const int* ei = (const int*)eiv;
        src = __ldg(&ei[e]);
        dst = __ldg(&ei[NE + e]);
    }
    float4 v = x[src * 16 + g];
    float* p = g_agg + (size_t)dst * CH + g * 4;
    asm volatile("red.global.add.v4.f32 [%0], {%1,%2,%3,%4};"
                 :: "l"(p), "f"(v.x), "f"(v.y), "f"(v.z), "f"(v.w)
                 : "memory");
}

// ---------------------------------------------------------------------------
// Kernel 3: fused MLP + gate — register-blocked.
// 256 threads = 16 j-groups x 16 r-groups; each thread: 4 output channels
// (t*4..t*4+3) for 4 nodes (r*4..r*4+3) -> 64-node tile per block iter.
// Inner loop unrolled by 4 in k: 4 weight LDS.128 + 4 act LDS.128 -> 64 FMA.
// Single activation buffer; layer-1 result held in regs across the sync,
// then written back in place.
// Dynamic smem: W1|W2|b1|b2|hs[64][68]  = 50.3 KB.
// ---------------------------------------------------------------------------
#define NPT 64        // nodes per tile
#define RPT 4         // nodes per thread
#define TPB 256
#define HS_STRIDE 68

#define SMEM_FLOATS (2 * CH * CH + 2 * CH + NPT * HS_STRIDE)

__global__ void __launch_bounds__(TPB)
mlp_k(const float* __restrict__ W1, const float* __restrict__ b1,
      const float* __restrict__ W2, const float* __restrict__ b2,
      const float* __restrict__ alpha, float* __restrict__ out,
      int out_size) {
    extern __shared__ float smem[];
    float* sW1 = smem;                       // 4096
    float* sW2 = sW1 + CH * CH;              // 4096
    float* sb1 = sW2 + CH * CH;              // 64
    float* sb2 = sb1 + CH;                   // 64
    float* hs  = sb2 + CH;                   // 64 x 68

    const int tid = threadIdx.x;
    for (int i = tid; i < CH * CH; i += TPB) {
        sW1[i] = W1[i];
        sW2[i] = W2[i];
    }
    if (tid < CH) { sb1[tid] = b1[tid]; sb2[tid] = b2[tid]; }
    const float gate = 1.0f / (1.0f + expf(-alpha[0]));
    __syncthreads();

    const int t  = tid & 15;       // j-group
    const int r  = tid >> 4;       // node-group
    const int j4 = t * 4;
    const int nb = r * RPT;        // first node (within tile) for this thread

    for (int base = blockIdx.x * NPT; base < NN; base += gridDim.x * NPT) {
        // ---- load tile: hs[row][:] = g_agg[base+row][:]  (coalesced) ----
        for (int i = tid; i < NPT * 16; i += TPB) {
            const int row = i >> 4, g = i & 15;
            const int node = base + row;
            if (node < NN) {
                *reinterpret_cast<float4*>(&hs[row * HS_STRIDE + g * 4]) =
                    *reinterpret_cast<const float4*>(
                        g_agg + (size_t)node * CH + g * 4);
            }
        }
        __syncthreads();

        // ---- layer 1: acc = relu(h @ W1 + b1), result kept in regs ----
        float4 acc[RPT];
        {
            const float4 bb = *reinterpret_cast<const float4*>(&sb1[j4]);
            #pragma unroll
            for (int n = 0; n < RPT; n++) acc[n] = bb;
        }
        #pragma unroll
        for (int k = 0; k < CH; k += 4) {
            const float4 w0 = *reinterpret_cast<const float4*>(&sW1[(k + 0) * CH + j4]);
            const float4 w1 = *reinterpret_cast<const float4*>(&sW1[(k + 1) * CH + j4]);
            const float4 w2 = *reinterpret_cast<const float4*>(&sW1[(k + 2) * CH + j4]);
            const float4 w3 = *reinterpret_cast<const float4*>(&sW1[(k + 3) * CH + j4]);
            #pragma unroll
            for (int n = 0; n < RPT; n++) {
                const float4 a = *reinterpret_cast<const float4*>(
                    &hs[(nb + n) * HS_STRIDE + k]);
                acc[n].x += a.x * w0.x + a.y * w1.x + a.z * w2.x + a.w * w3.x;
                acc[n].y += a.x * w0.y + a.y * w1.y + a.z * w2.y + a.w * w3.y;
                acc[n].z += a.x * w0.z + a.y * w1.z + a.z * w2.z + a.w * w3.z;
                acc[n].w += a.x * w0.w + a.y * w1.w + a.z * w2.w + a.w * w3.w;
            }
        }
        __syncthreads();   // everyone done reading hs
        #pragma unroll
        for (int n = 0; n < RPT; n++) {
            float4 v = acc[n];
            v.x = fmaxf(v.x, 0.0f); v.y = fmaxf(v.y, 0.0f);
            v.z = fmaxf(v.z, 0.0f); v.w = fmaxf(v.w, 0.0f);
            *reinterpret_cast<float4*>(&hs[(nb + n) * HS_STRIDE + j4]) = v;
        }
        __syncthreads();

        // ---- layer 2: out = gate * (h1 @ W2 + b2) ----
        {
            const float4 bb = *reinterpret_cast<const float4*>(&sb2[j4]);
            #pragma unroll
            for (int n = 0; n < RPT; n++) acc[n] = bb;
        }
        #pragma unroll
        for (int k = 0; k < CH; k += 4) {
            const float4 w0 = *reinterpret_cast<const float4*>(&sW2[(k + 0) * CH + j4]);
            const float4 w1 = *reinterpret_cast<const float4*>(&sW2[(k + 1) * CH + j4]);
            const float4 w2 = *reinterpret_cast<const float4*>(&sW2[(k + 2) * CH + j4]);
            const float4 w3 = *reinterpret_cast<const float4*>(&sW2[(k + 3) * CH + j4]);
            #pragma unroll
            for (int n = 0; n < RPT; n++) {
                const float4 a = *reinterpret_cast<const float4*>(
                    &hs[(nb + n) * HS_STRIDE + k]);
                acc[n].x += a.x * w0.x + a.y * w1.x + a.z * w2.x + a.w * w3.x;
                acc[n].y += a.x * w0.y + a.y * w1.y + a.z * w2.y + a.w * w3.y;
                acc[n].z += a.x * w0.z + a.y * w1.z + a.z * w2.z + a.w * w3.z;
                acc[n].w += a.x * w0.w + a.y * w1.w + a.z * w2.w + a.w * w3.w;
            }
        }
        #pragma unroll
        for (int n = 0; n < RPT; n++) {
            const int node = base + nb + n;
            if (node < NN) {
                float4 o = make_float4(gate * acc[n].x, gate * acc[n].y,
                                       gate * acc[n].z, gate * acc[n].w);
                *reinterpret_cast<float4*>(out + (size_t)node * CH + j4) = o;
            }
        }
        __syncthreads();   // protect hs before next tile
    }

    // Tail: reference also returns gate (flattened after main output).
    const int extra = out_size - NN * CH;
    if (blockIdx.x == 0 && tid < extra) out[NN * CH + tid] = gate;
}

// ---------------------------------------------------------------------------
extern "C" void kernel_launch(void* const* d_in, const int* in_sizes, int n_in,
                              void* d_out, int out_size) {
    const float* x     = (const float*)d_in[0];
    const void*  ei    = d_in[1];
    const float* W1    = (const float*)d_in[2];
    const float* b1    = (const float*)d_in[3];
    const float* W2    = (const float*)d_in[4];
    const float* b2    = (const float*)d_in[5];
    const float* alpha = (const float*)d_in[6];
    float*       out   = (float*)d_out;

    detect_k<<<1, 32>>>((const unsigned long long*)ei);

    init_agg_k<<<(NN * CH / 4 + 255) / 256, 256>>>(
        reinterpret_cast<const float4*>(x));

    scatter_k<<<(NE * 16 + 255) / 256, 256>>>(
        reinterpret_cast<const float4*>(x), ei);

    static const size_t smem_bytes = SMEM_FLOATS * sizeof(float);
    cudaFuncSetAttribute(mlp_k, cudaFuncAttributeMaxDynamicSharedMemorySize,
                         (int)smem_bytes);
    mlp_k<<<592, TPB, smem_bytes>>>(W1, b1, W2, b2, alpha, out, out_size);
}

// round 8
// speedup vs baseline: 1.6008x; 1.1262x over previous
#include <cuda_runtime.h>

#define NN 100000
#define NE 1600000
#define CH 64
#define NB_SCAN 98   // ceil(NN/1024)

// Device scratch (no allocs allowed)
__device__ float g_agg[(size_t)NN * CH];     // h = x + segment_sum
__device__ int   g_cnt[NN];                  // histogram, then write cursors
__device__ int   g_off[NN];                  // exclusive offsets
__device__ int   g_blksum[128];              // scan block sums
__device__ int   g_srt[NE];                  // src ids sorted by dst
__device__ int   g_idx_is64;

// ---------------------------------------------------------------------------
// Kernel 0: detect int64-vs-int32 edge_index (JAX x64-off narrows to int32).
// ---------------------------------------------------------------------------
__global__ void detect_k(const unsigned long long* __restrict__ ei) {
    if (threadIdx.x == 0 && blockIdx.x == 0) {
        int is64 = 1;
        for (int i = 0; i < 64; i++)
            if (ei[i] >= (unsigned long long)NN) { is64 = 0; break; }
        g_idx_is64 = is64;
    }
}

__device__ __forceinline__ int load_idx(const void* eiv, long long pos) {
    if (g_idx_is64) return (int)__ldg(&((const long long*)eiv)[pos]);
    return __ldg(&((const int*)eiv)[pos]);
}

// ---------------------------------------------------------------------------
// Sort pipeline: zero -> histogram -> block scan -> top scan -> add -> reorder
// ---------------------------------------------------------------------------
__global__ void zero_k() {
    int i = blockIdx.x * blockDim.x + threadIdx.x;
    if (i < NN) g_cnt[i] = 0;
}

__global__ void hist_k(const void* __restrict__ eiv) {
    int e = blockIdx.x * blockDim.x + threadIdx.x;
    if (e >= NE) return;
    int dst = load_idx(eiv, (long long)NE + e);
    atomicAdd(&g_cnt[dst], 1);
}

__global__ void __launch_bounds__(1024) scan_block_k() {
    __shared__ int warp_sums[32];
    const int tid = threadIdx.x;
    const int i = blockIdx.x * 1024 + tid;
    const int lane = tid & 31, warp = tid >> 5;
    int c = (i < NN) ? g_cnt[i] : 0;
    int v = c;
    #pragma unroll
    for (int d = 1; d < 32; d <<= 1) {
        int u = __shfl_up_sync(0xffffffffu, v, d);
        if (lane >= d) v += u;
    }
    if (lane == 31) warp_sums[warp] = v;
    __syncthreads();
    if (tid < 32) {
        int w = warp_sums[tid];
        #pragma unroll
        for (int d = 1; d < 32; d <<= 1) {
            int u = __shfl_up_sync(0xffffffffu, w, d);
            if (tid >= d) w += u;
        }
        warp_sums[tid] = w;  // inclusive per-warp totals
    }
    __syncthreads();
    const int wpref = warp ? warp_sums[warp - 1] : 0;
    if (i < NN) g_off[i] = wpref + v - c;      // exclusive within block
    if (tid == 1023) g_blksum[blockIdx.x] = wpref + v;
}

__global__ void scan_top_k() {   // 1 block, 128 threads over NB_SCAN sums
    __shared__ int ws[4];
    const int tid = threadIdx.x;
    const int lane = tid & 31, warp = tid >> 5;
    int c = (tid < NB_SCAN) ? g_blksum[tid] : 0;
    int v = c;
    #pragma unroll
    for (int d = 1; d < 32; d <<= 1) {
        int u = __shfl_up_sync(0xffffffffu, v, d);
        if (lane >= d) v += u;
    }
    if (lane == 31) ws[warp] = v;
    __syncthreads();
    if (tid == 0) {
        int s = 0;
        #pragma unroll
        for (int w = 0; w < 4; w++) { int t = ws[w]; ws[w] = s; s += t; }
    }
    __syncthreads();
    if (tid < NB_SCAN) g_blksum[tid] = ws[warp] + v - c;   // exclusive
}

__global__ void scan_add_k() {
    int i = blockIdx.x * blockDim.x + threadIdx.x;
    if (i < NN) {
        int o = g_off[i] + g_blksum[i >> 10];
        g_off[i] = o;
        g_cnt[i] = o;    // running cursor for reorder
    }
}

__global__ void reorder_k(const void* __restrict__ eiv) {
    int e = blockIdx.x * blockDim.x + threadIdx.x;
    if (e >= NE) return;
    int src = load_idx(eiv, e);
    int dst = load_idx(eiv, (long long)NE + e);
    int pos = atomicAdd(&g_cnt[dst], 1);
    g_srt[pos] = src;
}

// ---------------------------------------------------------------------------
// Aggregation: one warp per node, float2 per lane. Reads sorted src list,
// accumulates in registers, writes the 256B row ONCE (no atomics).
// ---------------------------------------------------------------------------
__global__ void __launch_bounds__(256) agg_k(const float2* __restrict__ x2) {
    const int gwarp = (blockIdx.x * 256 + threadIdx.x) >> 5;
    if (gwarp >= NN) return;
    const int lane = threadIdx.x & 31;
    const int off0 = __ldg(&g_off[gwarp]);
    const int off1 = (gwarp + 1 < NN) ? __ldg(&g_off[gwarp + 1]) : NE;

    float2 acc = x2[(size_t)gwarp * 32 + lane];   // self term (eps=0 GIN)
    int j = off0;
    for (; j + 4 <= off1; j += 4) {
        int s0 = __ldg(&g_srt[j + 0]);
        int s1 = __ldg(&g_srt[j + 1]);
        int s2 = __ldg(&g_srt[j + 2]);
        int s3 = __ldg(&g_srt[j + 3]);
        float2 v0 = x2[(size_t)s0 * 32 + lane];
        float2 v1 = x2[(size_t)s1 * 32 + lane];
        float2 v2 = x2[(size_t)s2 * 32 + lane];
        float2 v3 = x2[(size_t)s3 * 32 + lane];
        acc.x += (v0.x + v1.x) + (v2.x + v3.x);
        acc.y += (v0.y + v1.y) + (v2.y + v3.y);
    }
    for (; j < off1; j++) {
        int s = __ldg(&g_srt[j]);
        float2 v = x2[(size_t)s * 32 + lane];
        acc.x += v.x; acc.y += v.y;
    }
    *reinterpret_cast<float2*>(g_agg + (size_t)gwarp * CH + lane * 2) = acc;
}

// ---------------------------------------------------------------------------
// Kernel 3: fused MLP + gate — register-blocked (proven 60.1us version).
// 256 threads = 16 j-groups x 16 r-groups; each thread: 4 output channels
// for 4 nodes -> 64-node tile per block iter. Inner loop unrolled by 4 in k:
// 4 weight LDS.128 + 4 act LDS.128 -> 64 FMA.
// ---------------------------------------------------------------------------
#define NPT 64        // nodes per tile
#define RPT 4         // nodes per thread
#define TPB 256
#define HS_STRIDE 68

#define SMEM_FLOATS (2 * CH * CH + 2 * CH + NPT * HS_STRIDE)

__global__ void __launch_bounds__(TPB)
mlp_k(const float* __restrict__ W1, const float* __restrict__ b1,
      const float* __restrict__ W2, const float* __restrict__ b2,
      const float* __restrict__ alpha, float* __restrict__ out,
      int out_size) {
    extern __shared__ float smem[];
    float* sW1 = smem;                       // 4096
    float* sW2 = sW1 + CH * CH;              // 4096
    float* sb1 = sW2 + CH * CH;              // 64
    float* sb2 = sb1 + CH;                   // 64
    float* hs  = sb2 + CH;                   // 64 x 68

    const int tid = threadIdx.x;
    for (int i = tid; i < CH * CH; i += TPB) {
        sW1[i] = W1[i];
        sW2[i] = W2[i];
    }
    if (tid < CH) { sb1[tid] = b1[tid]; sb2[tid] = b2[tid]; }
    const float gate = 1.0f / (1.0f + expf(-alpha[0]));
    __syncthreads();

    const int t  = tid & 15;       // j-group
    const int r  = tid >> 4;       // node-group
    const int j4 = t * 4;
    const int nb = r * RPT;        // first node (within tile) for this thread

    for (int base = blockIdx.x * NPT; base < NN; base += gridDim.x * NPT) {
        // ---- load tile: hs[row][:] = g_agg[base+row][:]  (coalesced) ----
        for (int i = tid; i < NPT * 16; i += TPB) {
            const int row = i >> 4, g = i & 15;
            const int node = base + row;
            if (node < NN) {
                *reinterpret_cast<float4*>(&hs[row * HS_STRIDE + g * 4]) =
                    *reinterpret_cast<const float4*>(
                        g_agg + (size_t)node * CH + g * 4);
            }
        }
        __syncthreads();

        // ---- layer 1: acc = relu(h @ W1 + b1), result kept in regs ----
        float4 acc[RPT];
        {
            const float4 bb = *reinterpret_cast<const float4*>(&sb1[j4]);
            #pragma unroll
            for (int n = 0; n < RPT; n++) acc[n] = bb;
        }
        #pragma unroll
        for (int k = 0; k < CH; k += 4) {
            const float4 w0 = *reinterpret_cast<const float4*>(&sW1[(k + 0) * CH + j4]);
            const float4 w1 = *reinterpret_cast<const float4*>(&sW1[(k + 1) * CH + j4]);
            const float4 w2 = *reinterpret_cast<const float4*>(&sW1[(k + 2) * CH + j4]);
            const float4 w3 = *reinterpret_cast<const float4*>(&sW1[(k + 3) * CH + j4]);
            #pragma unroll
            for (int n = 0; n < RPT; n++) {
                const float4 a = *reinterpret_cast<const float4*>(
                    &hs[(nb + n) * HS_STRIDE + k]);
                acc[n].x += a.x * w0.x + a.y * w1.x + a.z * w2.x + a.w * w3.x;
                acc[n].y += a.x * w0.y + a.y * w1.y + a.z * w2.y + a.w * w3.y;
                acc[n].z += a.x * w0.z + a.y * w1.z + a.z * w2.z + a.w * w3.z;
                acc[n].w += a.x * w0.w + a.y * w1.w + a.z * w2.w + a.w * w3.w;
            }
        }
        __syncthreads();   // everyone done reading hs
        #pragma unroll
        for (int n = 0; n < RPT; n++) {
            float4 v = acc[n];
            v.x = fmaxf(v.x, 0.0f); v.y = fmaxf(v.y, 0.0f);
            v.z = fmaxf(v.z, 0.0f); v.w = fmaxf(v.w, 0.0f);
            *reinterpret_cast<float4*>(&hs[(nb + n) * HS_STRIDE + j4]) = v;
        }
        __syncthreads();

        // ---- layer 2: out = gate * (h1 @ W2 + b2) ----
        {
            const float4 bb = *reinterpret_cast<const float4*>(&sb2[j4]);
            #pragma unroll
            for (int n = 0; n < RPT; n++) acc[n] = bb;
        }
        #pragma unroll
        for (int k = 0; k < CH; k += 4) {
            const float4 w0 = *reinterpret_cast<const float4*>(&sW2[(k + 0) * CH + j4]);
            const float4 w1 = *reinterpret_cast<const float4*>(&sW2[(k + 1) * CH + j4]);
            const float4 w2 = *reinterpret_cast<const float4*>(&sW2[(k + 2) * CH + j4]);
            const float4 w3 = *reinterpret_cast<const float4*>(&sW2[(k + 3) * CH + j4]);
            #pragma unroll
            for (int n = 0; n < RPT; n++) {
                const float4 a = *reinterpret_cast<const float4*>(
                    &hs[(nb + n) * HS_STRIDE + k]);
                acc[n].x += a.x * w0.x + a.y * w1.x + a.z * w2.x + a.w * w3.x;
                acc[n].y += a.x * w0.y + a.y * w1.y + a.z * w2.y + a.w * w3.y;
                acc[n].z += a.x * w0.z + a.y * w1.z + a.z * w2.z + a.w * w3.z;
                acc[n].w += a.x * w0.w + a.y * w1.w + a.z * w2.w + a.w * w3.w;
            }
        }
        #pragma unroll
        for (int n = 0; n < RPT; n++) {
            const int node = base + nb + n;
            if (node < NN) {
                float4 o = make_float4(gate * acc[n].x, gate * acc[n].y,
                                       gate * acc[n].z, gate * acc[n].w);
                *reinterpret_cast<float4*>(out + (size_t)node * CH + j4) = o;
            }
        }
        __syncthreads();   // protect hs before next tile
    }

    // Tail: reference also returns gate (flattened after main output).
    const int extra = out_size - NN * CH;
    if (blockIdx.x == 0 && tid < extra) out[NN * CH + tid] = gate;
}

// ---------------------------------------------------------------------------
extern "C" void kernel_launch(void* const* d_in, const int* in_sizes, int n_in,
                              void* d_out, int out_size) {
    const float* x     = (const float*)d_in[0];
    const void*  ei    = d_in[1];
    const float* W1    = (const float*)d_in[2];
    const float* b1    = (const float*)d_in[3];
    const float* W2    = (const float*)d_in[4];
    const float* b2    = (const float*)d_in[5];
    const float* alpha = (const float*)d_in[6];
    float*       out   = (float*)d_out;

    detect_k<<<1, 32>>>((const unsigned long long*)ei);

    zero_k<<<(NN + 255) / 256, 256>>>();
    hist_k<<<(NE + 255) / 256, 256>>>(ei);
    scan_block_k<<<NB_SCAN, 1024>>>();
    scan_top_k<<<1, 128>>>();
    scan_add_k<<<(NN + 255) / 256, 256>>>();
    reorder_k<<<(NE + 255) / 256, 256>>>(ei);

    agg_k<<<(NN * 32 + 255) / 256, 256>>>(
        reinterpret_cast<const float2*>(x));

    static const size_t smem_bytes = SMEM_FLOATS * sizeof(float);
    cudaFuncSetAttribute(mlp_k, cudaFuncAttributeMaxDynamicSharedMemorySize,
                         (int)smem_bytes);
    mlp_k<<<592, TPB, smem_bytes>>>(W1, b1, W2, b2, alpha, out, out_size);
}